// round 2
// baseline (speedup 1.0000x reference)
#include <cuda_runtime.h>
#include <cuda_bf16.h>
#include <cstdint>

// Problem constants
#define B    2
#define N    512
#define MV   512
#define DIN  256
#define H    16
#define DOUT 128
#define LN_EPS 1e-5f

// Scratch: proj = [B*N][32] (a = cols 0..15, bq = cols 16..31); T = [B][M][16 p][128 d]
__device__ float g_proj[B * N * 2 * H];            // 128 KB
__device__ float g_T[B * MV * H * DOUT];           // 8 MB

// packed f32x2 FMA: d = a*b + c lanewise on two fp32 packed in a 64-bit reg
#define FMA_F32X2(d_, a_, b_, c_) \
    asm("fma.rn.f32x2 %0, %1, %2, %3;" : "=l"(d_) : "l"(a_), "l"(b_), "l"(c_))

// duplicate one fp32 into both lanes of an f32x2 pack (single MOV, ALU pipe)
#define DUP_F32X2(d_, f_) \
    asm("mov.b64 %0, {%1, %1};" : "=l"(d_) : "f"(f_))

// ---------------------------------------------------------------------------
// Kernel 1: LayerNorm + input projection.  Warp per row, 8 rows per block.
// proj[r][j] = b_in[j] + sum_i xhat[r][i]*W_in[i][j]
// ---------------------------------------------------------------------------
__global__ __launch_bounds__(256) void k_proj(
    const float* __restrict__ feats, const float* __restrict__ gamma,
    const float* __restrict__ beta,  const float* __restrict__ W_in,
    const float* __restrict__ b_in,  float* __restrict__ proj)
{
    __shared__ __align__(16) float xs[8][DIN];
    int w    = threadIdx.x >> 5;
    int lane = threadIdx.x & 31;
    int r    = blockIdx.x * 8 + w;

    const float4* f4 = (const float4*)(feats + (size_t)r * DIN);
    float4 va = f4[lane * 2], vb = f4[lane * 2 + 1];

    float s  = va.x + va.y + va.z + va.w + vb.x + vb.y + vb.z + vb.w;
    float s2 = va.x*va.x + va.y*va.y + va.z*va.z + va.w*va.w
             + vb.x*vb.x + vb.y*vb.y + vb.z*vb.z + vb.w*vb.w;
    #pragma unroll
    for (int o = 16; o; o >>= 1) {
        s  += __shfl_xor_sync(0xFFFFFFFFu, s,  o);
        s2 += __shfl_xor_sync(0xFFFFFFFFu, s2, o);
    }
    float mu  = s  * (1.f / DIN);
    float var = s2 * (1.f / DIN) - mu * mu;
    float rs  = rsqrtf(var + LN_EPS);

    const float4* g4 = (const float4*)gamma;
    const float4* b4 = (const float4*)beta;
    float4 ga = g4[lane * 2], gb = g4[lane * 2 + 1];
    float4 ba = b4[lane * 2], bb = b4[lane * 2 + 1];

    int i0 = lane * 8;
    xs[w][i0 + 0] = (va.x - mu) * rs * ga.x + ba.x;
    xs[w][i0 + 1] = (va.y - mu) * rs * ga.y + ba.y;
    xs[w][i0 + 2] = (va.z - mu) * rs * ga.z + ba.z;
    xs[w][i0 + 3] = (va.w - mu) * rs * ga.w + ba.w;
    xs[w][i0 + 4] = (vb.x - mu) * rs * gb.x + bb.x;
    xs[w][i0 + 5] = (vb.y - mu) * rs * gb.y + bb.y;
    xs[w][i0 + 6] = (vb.z - mu) * rs * gb.z + bb.z;
    xs[w][i0 + 7] = (vb.w - mu) * rs * gb.w + bb.w;
    __syncwarp();

    // j = lane; out_j = b_in[j] + sum_i xs[i] * W_in[i*32 + j]
    float acc = b_in[lane];
    #pragma unroll 8
    for (int i = 0; i < DIN; i++)
        acc = fmaf(xs[w][i], W_in[i * 32 + lane], acc);
    proj[r * 32 + lane] = acc;
}

// ---------------------------------------------------------------------------
// Kernel 2: T[b][m][p][d] = sum_q W_out[d][p*16+q] * bq[b][m][q]
// Grid: B * (M/8) = 128 blocks, 256 threads. Each block: 8 m values.
// ---------------------------------------------------------------------------
__global__ __launch_bounds__(256) void k_T(
    const float* __restrict__ proj, const float* __restrict__ W_out,
    float* __restrict__ T)
{
    int bm = blockIdx.x;           // 0..127
    int b  = bm >> 6;              // 64 m-groups per b
    int m0 = (bm & 63) * 8;
    int t  = threadIdx.x;

    __shared__ float bq[8][16];
    if (t < 128) {
        int mm = t >> 4, q = t & 15;
        bq[mm][q] = proj[(b * N + m0 + mm) * 32 + 16 + q];
    }
    __syncthreads();

    int d = t & 127, ph = t >> 7;  // ph selects p-range
    #pragma unroll
    for (int pi = 0; pi < 8; pi++) {
        int p = ph * 8 + pi;
        const float4* wp = (const float4*)&W_out[d * 256 + p * 16];
        float4 w0 = wp[0], w1 = wp[1], w2 = wp[2], w3 = wp[3];
        float w[16] = { w0.x,w0.y,w0.z,w0.w, w1.x,w1.y,w1.z,w1.w,
                        w2.x,w2.y,w2.z,w2.w, w3.x,w3.y,w3.z,w3.w };
        #pragma unroll
        for (int mm = 0; mm < 8; mm++) {
            float acc = 0.f;
            #pragma unroll
            for (int q = 0; q < 16; q++) acc = fmaf(w[q], bq[mm][q], acc);
            T[(((b * N) + (m0 + mm)) * H + p) * DOUT + d] = acc;
        }
    }
}

// ---------------------------------------------------------------------------
// Kernel 3: main contraction, v2.
// out[b,n,m,d] = b_out[d] + sum_p a[b,n,p] * T[b,m,p,d]
// Grid = B * M * 8 n-blocks = 8192 CTAs, 256 threads.
// Warp  = one 16-d group (uniform T loads) x 32 n-pairs.
// Thread = 2 n x 16 d; `a` register-resident for the whole p-loop.
// ---------------------------------------------------------------------------
__global__ __launch_bounds__(256, 2) void k_main(
    const float* __restrict__ proj, const float* __restrict__ Tg,
    const float* __restrict__ b_out, float* __restrict__ out)
{
    int job = blockIdx.x;          // 0..8191
    int b   = job >> 12;
    int m   = (job >> 3) & 511;
    int n0  = (job & 7) * 64;
    int t   = threadIdx.x;
    int w   = t >> 5;              // d-group: d = w*16 .. w*16+15
    int lane = t & 31;             // n-pair within the 64-n block

    __shared__ __align__(16) float Ts[H * DOUT];   // 8 KB, plain [p][d]

    // ---- load a (rows n_0, n_0+1), kept in registers across the p-loop ----
    int n_0 = n0 + lane * 2;
    const float4* ap0 = (const float4*)(proj + (size_t)(b * N + n_0) * 32);
    const float4* ap1 = (const float4*)(proj + (size_t)(b * N + n_0 + 1) * 32);
    float4 a0v[4] = { ap0[0], ap0[1], ap0[2], ap0[3] };
    float4 a1v[4] = { ap1[0], ap1[1], ap1[2], ap1[3] };
    float a0f[16] = { a0v[0].x,a0v[0].y,a0v[0].z,a0v[0].w,
                      a0v[1].x,a0v[1].y,a0v[1].z,a0v[1].w,
                      a0v[2].x,a0v[2].y,a0v[2].z,a0v[2].w,
                      a0v[3].x,a0v[3].y,a0v[3].z,a0v[3].w };
    float a1f[16] = { a1v[0].x,a1v[0].y,a1v[0].z,a1v[0].w,
                      a1v[1].x,a1v[1].y,a1v[1].z,a1v[1].w,
                      a1v[2].x,a1v[2].y,a1v[2].z,a1v[2].w,
                      a1v[3].x,a1v[3].y,a1v[3].z,a1v[3].w };

    // ---- stage T tile (8 KB), linear copy ----
    {
        const float4* Tsrc = (const float4*)(Tg + (size_t)(b * N + m) * (H * DOUT));
        float4* Td = (float4*)Ts;
        Td[t]       = Tsrc[t];
        Td[t + 256] = Tsrc[t + 256];
    }
    __syncthreads();

    // ---- acc init = b_out (16 d as 8 f32x2 pairs, per n) ----
    unsigned long long acc0[8], acc1[8];
    {
        const unsigned long long* bo =
            (const unsigned long long*)(b_out + w * 16);
        #pragma unroll
        for (int k = 0; k < 8; k++) { acc0[k] = bo[k]; acc1[k] = bo[k]; }
    }

    // ---- main loop over p: T loads warp-uniform (broadcast), a in regs ----
    #pragma unroll
    for (int p = 0; p < H; p++) {
        const ulonglong2* tp = (const ulonglong2*)&Ts[p * DOUT + w * 16];
        ulonglong2 t01 = tp[0], t23 = tp[1], t45 = tp[2], t67 = tp[3];
        unsigned long long tv[8] = { t01.x, t01.y, t23.x, t23.y,
                                     t45.x, t45.y, t67.x, t67.y };
        unsigned long long ad0, ad1;
        DUP_F32X2(ad0, a0f[p]);
        DUP_F32X2(ad1, a1f[p]);
        #pragma unroll
        for (int k = 0; k < 8; k++) {
            FMA_F32X2(acc0[k], ad0, tv[k], acc0[k]);
            FMA_F32X2(acc1[k], ad1, tv[k], acc1[k]);
        }
    }

    // ---- store: 2 rows x 64B contiguous each ----
    size_t base = (((size_t)(b * N) + n_0) * MV + m) * (size_t)DOUT + w * 16;
    ulonglong2* o0 = (ulonglong2*)(out + base);
    ulonglong2* o1 = (ulonglong2*)(out + base + (size_t)MV * DOUT);
    o0[0] = make_ulonglong2(acc0[0], acc0[1]);
    o0[1] = make_ulonglong2(acc0[2], acc0[3]);
    o0[2] = make_ulonglong2(acc0[4], acc0[5]);
    o0[3] = make_ulonglong2(acc0[6], acc0[7]);
    o1[0] = make_ulonglong2(acc1[0], acc1[1]);
    o1[1] = make_ulonglong2(acc1[2], acc1[3]);
    o1[2] = make_ulonglong2(acc1[4], acc1[5]);
    o1[3] = make_ulonglong2(acc1[6], acc1[7]);
}

// ---------------------------------------------------------------------------
extern "C" void kernel_launch(void* const* d_in, const int* in_sizes, int n_in,
                              void* d_out, int out_size)
{
    const float* feats  = (const float*)d_in[0];
    const float* gamma  = (const float*)d_in[1];
    const float* beta   = (const float*)d_in[2];
    const float* W_in   = (const float*)d_in[3];
    const float* b_in   = (const float*)d_in[4];
    const float* W_out  = (const float*)d_in[5];
    const float* b_out  = (const float*)d_in[6];
    float* out = (float*)d_out;

    float* proj; cudaGetSymbolAddress((void**)&proj, g_proj);
    float* T;    cudaGetSymbolAddress((void**)&T,    g_T);

    k_proj<<<(B * N) / 8, 256>>>(feats, gamma, beta, W_in, b_in, proj);
    k_T<<<B * (MV / 8), 256>>>(proj, W_out, T);
    k_main<<<B * MV * 8, 256>>>(proj, T, b_out, out);
}

// round 3
// speedup vs baseline: 1.1561x; 1.1561x over previous
#include <cuda_runtime.h>
#include <cuda_bf16.h>
#include <cstdint>

// Problem constants
#define B    2
#define N    512
#define MV   512
#define DIN  256
#define H    16
#define DOUT 128
#define LN_EPS 1e-5f

// Scratch: proj = [B*N][32] (a = cols 0..15, bq = cols 16..31); T = [B][M][16 p][128 d]
__device__ float g_proj[B * N * 2 * H];            // 128 KB
__device__ float g_T[B * MV * H * DOUT];           // 8 MB

// packed f32x2 FMA: d = a*b + c lanewise on two fp32 packed in a 64-bit reg
#define FMA_F32X2(d_, a_, b_, c_) \
    asm("fma.rn.f32x2 %0, %1, %2, %3;" : "=l"(d_) : "l"(a_), "l"(b_), "l"(c_))

// duplicate one fp32 into both lanes of an f32x2 pack (single MOV, ALU pipe)
#define DUP_F32X2(d_, f_) \
    asm("mov.b64 %0, {%1, %1};" : "=l"(d_) : "f"(f_))

// ---------------------------------------------------------------------------
// Kernel 1: LayerNorm + input projection.  One block per row (B*N = 1024 rows).
// proj[r][j] = b_in[j] + sum_i xhat[r][i]*W_in[i][j]   (R1 version, 7us known)
// ---------------------------------------------------------------------------
__global__ __launch_bounds__(256) void k_proj(
    const float* __restrict__ feats, const float* __restrict__ gamma,
    const float* __restrict__ beta,  const float* __restrict__ W_in,
    const float* __restrict__ b_in,  float* __restrict__ proj)
{
    int r = blockIdx.x;            // 0..1023
    int t = threadIdx.x;           // 0..255
    __shared__ float xs[DIN];
    __shared__ float ws[8], ws2[8];
    __shared__ float ps[8][32];

    float v = feats[r * DIN + t];
    float s = v, s2 = v * v;
    #pragma unroll
    for (int o = 16; o; o >>= 1) {
        s  += __shfl_xor_sync(0xFFFFFFFFu, s,  o);
        s2 += __shfl_xor_sync(0xFFFFFFFFu, s2, o);
    }
    if ((t & 31) == 0) { ws[t >> 5] = s; ws2[t >> 5] = s2; }
    __syncthreads();
    float ts = 0.f, ts2 = 0.f;
    #pragma unroll
    for (int i = 0; i < 8; i++) { ts += ws[i]; ts2 += ws2[i]; }
    float mu  = ts * (1.f / DIN);
    float var = ts2 * (1.f / DIN) - mu * mu;
    float rs  = rsqrtf(var + LN_EPS);
    xs[t] = (v - mu) * rs * gamma[t] + beta[t];
    __syncthreads();

    int j = t & 31, seg = t >> 5;
    float acc = 0.f;
    #pragma unroll 8
    for (int i = seg * 32; i < seg * 32 + 32; i++)
        acc = fmaf(xs[i], W_in[i * 32 + j], acc);
    ps[seg][j] = acc;
    __syncthreads();
    if (seg == 0) {
        float tot = b_in[j];
        #pragma unroll
        for (int i = 0; i < 8; i++) tot += ps[i][j];
        proj[r * 32 + j] = tot;
    }
}

// ---------------------------------------------------------------------------
// Kernel 2: T[b][m][p][d] = sum_q W_out[d][p*16+q] * bq[b][m][q]
// Grid: B * (M/8) = 128 blocks, 256 threads. Each block: 8 m values.
// ---------------------------------------------------------------------------
__global__ __launch_bounds__(256) void k_T(
    const float* __restrict__ proj, const float* __restrict__ W_out,
    float* __restrict__ T)
{
    int bm = blockIdx.x;           // 0..127
    int b  = bm >> 6;              // 64 m-groups per b
    int m0 = (bm & 63) * 8;
    int t  = threadIdx.x;

    __shared__ float bq[8][16];
    if (t < 128) {
        int mm = t >> 4, q = t & 15;
        bq[mm][q] = proj[(b * N + m0 + mm) * 32 + 16 + q];
    }
    __syncthreads();

    int d = t & 127, ph = t >> 7;  // ph selects p-range
    #pragma unroll
    for (int pi = 0; pi < 8; pi++) {
        int p = ph * 8 + pi;
        const float4* wp = (const float4*)&W_out[d * 256 + p * 16];
        float4 w0 = wp[0], w1 = wp[1], w2 = wp[2], w3 = wp[3];
        float w[16] = { w0.x,w0.y,w0.z,w0.w, w1.x,w1.y,w1.z,w1.w,
                        w2.x,w2.y,w2.z,w2.w, w3.x,w3.y,w3.z,w3.w };
        #pragma unroll
        for (int mm = 0; mm < 8; mm++) {
            float acc = 0.f;
            #pragma unroll
            for (int q = 0; q < 16; q++) acc = fmaf(w[q], bq[mm][q], acc);
            T[(((b * N) + (m0 + mm)) * H + p) * DOUT + d] = acc;
        }
    }
}

// ---------------------------------------------------------------------------
// Kernel 3: main contraction, v3.
// out[b,n,m,d] = b_out[d] + sum_p a[b,n,p] * T[b,m,p,d]
// Grid = B * M * 8 n-blocks = 8192 CTAs, 256 threads.
// Warp  = 8 n-rows x 128 d.  Lane -> (rquad = lane>>3, chunk dc = lane&7).
// Thread = rows {r0, r0+4} x 16 contiguous d (dc*16..dc*16+15).
//   -> fully coalesced 512B-row stores, conflict-free broadcast LDS of T,
//      `a` register-resident across the whole p-loop.
// Ts smem layout: word(p, sub, chunk, j) = p*128 + sub*32 + chunk*4 + j
//   where original d = chunk*16 + sub*4 + j.
// ---------------------------------------------------------------------------
__global__ __launch_bounds__(256, 2) void k_main(
    const float* __restrict__ proj, const float* __restrict__ Tg,
    const float* __restrict__ b_out, float* __restrict__ out)
{
    int job  = blockIdx.x;          // 0..8191
    int b    = job >> 12;
    int m    = (job >> 3) & 511;
    int n0   = (job & 7) * 64;
    int t    = threadIdx.x;
    int w    = t >> 5;
    int lane = t & 31;
    int rq   = lane >> 3;           // 0..3
    int dc   = lane & 7;            // d-chunk: d = dc*16 .. dc*16+15

    __shared__ __align__(16) float Ts[H * DOUT];    // 8 KB, sub-interleaved

    // ---- rows handled by this thread ----
    int r0 = n0 + w * 8 + rq;       // and r1 = r0 + 4

    // ---- load a (rows r0, r0+4) into registers for the whole p-loop ----
    const float4* ap0 = (const float4*)(proj + (size_t)(b * N + r0) * 32);
    const float4* ap1 = (const float4*)(proj + (size_t)(b * N + r0 + 4) * 32);
    float4 a0v[4] = { ap0[0], ap0[1], ap0[2], ap0[3] };
    float4 a1v[4] = { ap1[0], ap1[1], ap1[2], ap1[3] };
    float a0f[16] = { a0v[0].x,a0v[0].y,a0v[0].z,a0v[0].w,
                      a0v[1].x,a0v[1].y,a0v[1].z,a0v[1].w,
                      a0v[2].x,a0v[2].y,a0v[2].z,a0v[2].w,
                      a0v[3].x,a0v[3].y,a0v[3].z,a0v[3].w };
    float a1f[16] = { a1v[0].x,a1v[0].y,a1v[0].z,a1v[0].w,
                      a1v[1].x,a1v[1].y,a1v[1].z,a1v[1].w,
                      a1v[2].x,a1v[2].y,a1v[2].z,a1v[2].w,
                      a1v[3].x,a1v[3].y,a1v[3].z,a1v[3].w };

    // ---- stage T tile (8 KB) into sub-interleaved layout ----
    {
        const float4* Tsrc = (const float4*)(Tg + (size_t)(b * N + m) * (H * DOUT));
        float4* Td = (float4*)Ts;
        #pragma unroll
        for (int pass = 0; pass < 2; pass++) {
            int i    = t + pass * 256;       // 0..511 float4 index
            int p    = i >> 5;
            int d4   = i & 31;               // d/4
            int chnk = d4 >> 2;
            int sub  = d4 & 3;
            Td[p * 32 + sub * 8 + chnk] = Tsrc[i];
        }
    }
    __syncthreads();

    // ---- acc init = b_out[dc*16 .. +15] as 8 f32x2 pairs per row ----
    unsigned long long acc0[8], acc1[8];
    {
        const unsigned long long* bo =
            (const unsigned long long*)(b_out + dc * 16);
        #pragma unroll
        for (int k = 0; k < 8; k++) { acc0[k] = bo[k]; acc1[k] = bo[k]; }
    }

    // ---- main loop over p ----
    const ulonglong2* TU = (const ulonglong2*)Ts;   // 16B units
    #pragma unroll 2
    for (int p = 0; p < H; p++) {
        // 4 conflict-free LDS.128: sub s at unit index p*32 + s*8 + dc
        ulonglong2 q0 = TU[p * 32 + 0 * 8 + dc];
        ulonglong2 q1 = TU[p * 32 + 1 * 8 + dc];
        ulonglong2 q2 = TU[p * 32 + 2 * 8 + dc];
        ulonglong2 q3 = TU[p * 32 + 3 * 8 + dc];
        unsigned long long tv[8] = { q0.x, q0.y, q1.x, q1.y,
                                     q2.x, q2.y, q3.x, q3.y };
        unsigned long long ad0, ad1;
        DUP_F32X2(ad0, a0f[p]);
        DUP_F32X2(ad1, a1f[p]);
        #pragma unroll
        for (int k = 0; k < 8; k++) {
            FMA_F32X2(acc0[k], ad0, tv[k], acc0[k]);
            FMA_F32X2(acc1[k], ad1, tv[k], acc1[k]);
        }
    }

    // ---- coalesced stores: each row segment 64B, warp rows contiguous ----
    size_t base0 = (((size_t)(b * N) + r0) * MV + m) * (size_t)DOUT + dc * 16;
    size_t base1 = base0 + 4 * (size_t)MV * DOUT;
    ulonglong2* o0 = (ulonglong2*)(out + base0);
    ulonglong2* o1 = (ulonglong2*)(out + base1);
    o0[0] = make_ulonglong2(acc0[0], acc0[1]);
    o0[1] = make_ulonglong2(acc0[2], acc0[3]);
    o0[2] = make_ulonglong2(acc0[4], acc0[5]);
    o0[3] = make_ulonglong2(acc0[6], acc0[7]);
    o1[0] = make_ulonglong2(acc1[0], acc1[1]);
    o1[1] = make_ulonglong2(acc1[2], acc1[3]);
    o1[2] = make_ulonglong2(acc1[4], acc1[5]);
    o1[3] = make_ulonglong2(acc1[6], acc1[7]);
}

// ---------------------------------------------------------------------------
extern "C" void kernel_launch(void* const* d_in, const int* in_sizes, int n_in,
                              void* d_out, int out_size)
{
    const float* feats  = (const float*)d_in[0];
    const float* gamma  = (const float*)d_in[1];
    const float* beta   = (const float*)d_in[2];
    const float* W_in   = (const float*)d_in[3];
    const float* b_in   = (const float*)d_in[4];
    const float* W_out  = (const float*)d_in[5];
    const float* b_out  = (const float*)d_in[6];
    float* out = (float*)d_out;

    float* proj; cudaGetSymbolAddress((void**)&proj, g_proj);
    float* T;    cudaGetSymbolAddress((void**)&T,    g_T);

    k_proj<<<B * N, 256>>>(feats, gamma, beta, W_in, b_in, proj);
    k_T<<<B * (MV / 8), 256>>>(proj, W_out, T);
    k_main<<<B * MV * 8, 256>>>(proj, T, b_out, out);
}

// round 4
// speedup vs baseline: 1.8397x; 1.5912x over previous
#include <cuda_runtime.h>
#include <cuda_bf16.h>
#include <cstdint>

// Problem constants
#define B    2
#define N    512
#define MV   512
#define DIN  256
#define H    16
#define DOUT 128
#define LN_EPS 1e-5f

// Scratch: proj = [B*N][32] (a = cols 0..15, bq = cols 16..31); T = [B][M][16 p][128 d]
__device__ float g_proj[B * N * 2 * H];            // 128 KB
__device__ float g_T[B * MV * H * DOUT];           // 8 MB

// packed f32x2 FMA: d = a*b + c lanewise on two fp32 packed in a 64-bit reg
#define FMA_F32X2(d_, a_, b_, c_) \
    asm("fma.rn.f32x2 %0, %1, %2, %3;" : "=l"(d_) : "l"(a_), "l"(b_), "l"(c_))

// duplicate one fp32 into both lanes of an f32x2 pack (single MOV, ALU pipe)
#define DUP_F32X2(d_, f_) \
    asm("mov.b64 %0, {%1, %1};" : "=l"(d_) : "f"(f_))

// ---------------------------------------------------------------------------
// Kernel 1: LayerNorm + input projection.  One block per row (B*N = 1024 rows).
// proj[r][j] = b_in[j] + sum_i xhat[r][i]*W_in[i][j]
// ---------------------------------------------------------------------------
__global__ __launch_bounds__(256) void k_proj(
    const float* __restrict__ feats, const float* __restrict__ gamma,
    const float* __restrict__ beta,  const float* __restrict__ W_in,
    const float* __restrict__ b_in,  float* __restrict__ proj)
{
    int r = blockIdx.x;            // 0..1023
    int t = threadIdx.x;           // 0..255
    __shared__ float xs[DIN];
    __shared__ float ws[8], ws2[8];
    __shared__ float ps[8][32];

    float v = feats[r * DIN + t];
    float s = v, s2 = v * v;
    #pragma unroll
    for (int o = 16; o; o >>= 1) {
        s  += __shfl_xor_sync(0xFFFFFFFFu, s,  o);
        s2 += __shfl_xor_sync(0xFFFFFFFFu, s2, o);
    }
    if ((t & 31) == 0) { ws[t >> 5] = s; ws2[t >> 5] = s2; }
    __syncthreads();
    float ts = 0.f, ts2 = 0.f;
    #pragma unroll
    for (int i = 0; i < 8; i++) { ts += ws[i]; ts2 += ws2[i]; }
    float mu  = ts * (1.f / DIN);
    float var = ts2 * (1.f / DIN) - mu * mu;
    float rs  = rsqrtf(var + LN_EPS);
    xs[t] = (v - mu) * rs * gamma[t] + beta[t];
    __syncthreads();

    int j = t & 31, seg = t >> 5;
    float acc = 0.f;
    #pragma unroll 8
    for (int i = seg * 32; i < seg * 32 + 32; i++)
        acc = fmaf(xs[i], W_in[i * 32 + j], acc);
    ps[seg][j] = acc;
    __syncthreads();
    if (seg == 0) {
        float tot = b_in[j];
        #pragma unroll
        for (int i = 0; i < 8; i++) tot += ps[i][j];
        proj[r * 32 + j] = tot;
    }
}

// ---------------------------------------------------------------------------
// Kernel 2: T[b][m][p][d] = sum_q W_out[d][p*16+q] * bq[b][m][q]
// Grid: B * (M/8) = 128 blocks, 256 threads. Each block: 8 m values.
// ---------------------------------------------------------------------------
__global__ __launch_bounds__(256) void k_T(
    const float* __restrict__ proj, const float* __restrict__ W_out,
    float* __restrict__ T)
{
    int bm = blockIdx.x;           // 0..127
    int b  = bm >> 6;              // 64 m-groups per b
    int m0 = (bm & 63) * 8;
    int t  = threadIdx.x;

    __shared__ float bq[8][16];
    if (t < 128) {
        int mm = t >> 4, q = t & 15;
        bq[mm][q] = proj[(b * N + m0 + mm) * 32 + 16 + q];
    }
    __syncthreads();

    int d = t & 127, ph = t >> 7;  // ph selects p-range
    #pragma unroll
    for (int pi = 0; pi < 8; pi++) {
        int p = ph * 8 + pi;
        const float4* wp = (const float4*)&W_out[d * 256 + p * 16];
        float4 w0 = wp[0], w1 = wp[1], w2 = wp[2], w3 = wp[3];
        float w[16] = { w0.x,w0.y,w0.z,w0.w, w1.x,w1.y,w1.z,w1.w,
                        w2.x,w2.y,w2.z,w2.w, w3.x,w3.y,w3.z,w3.w };
        #pragma unroll
        for (int mm = 0; mm < 8; mm++) {
            float acc = 0.f;
            #pragma unroll
            for (int q = 0; q < 16; q++) acc = fmaf(w[q], bq[mm][q], acc);
            T[(((b * N) + (m0 + mm)) * H + p) * DOUT + d] = acc;
        }
    }
}

// ---------------------------------------------------------------------------
// Kernel 3: main contraction, v4.
// out[b,n,m,d] = b_out[d] + sum_p a[b,n,p] * T[b,m,p,d]
// Grid = B * M * 8 n-blocks = 8192 CTAs, 256 threads, occ 2.
// Warp = 8 n-rows x 128 d.  Lane -> (rq = lane>>3 row-quad, dc = lane&7).
// Thread = rows {r0, r0+4} x 4 d-chunks {8k+dc : k=0..3} (chunk = 4 floats).
//   -> every STG.128 is a dense 128B line per row-quad (4 rows x 128B),
//   -> LDS of T conflict-free in NATURAL [p][d] layout (8 lanes x 16B
//      contiguous = 32 banks once, 4-way broadcast across row-quads),
//   -> p-loop FULLY unrolled: a[] arrays register-promoted (no local mem).
// ---------------------------------------------------------------------------
__global__ __launch_bounds__(256, 2) void k_main(
    const float* __restrict__ proj, const float* __restrict__ Tg,
    const float* __restrict__ b_out, float* __restrict__ out)
{
    int job  = blockIdx.x;          // 0..8191
    int b    = job >> 12;
    int m    = (job >> 3) & 511;
    int n0   = (job & 7) * 64;
    int t    = threadIdx.x;
    int w    = t >> 5;
    int lane = t & 31;
    int rq   = lane >> 3;           // 0..3
    int dc   = lane & 7;            // 0..7

    __shared__ __align__(16) float Ts[H * DOUT];    // 8 KB, natural [p][d]

    int r0 = n0 + w * 8 + rq;       // rows r0 and r0+4

    // ---- load a (rows r0, r0+4), fully register-resident ----
    const float4* ap0 = (const float4*)(proj + (size_t)(b * N + r0) * 32);
    const float4* ap1 = (const float4*)(proj + (size_t)(b * N + r0 + 4) * 32);
    float4 a0v0 = ap0[0], a0v1 = ap0[1], a0v2 = ap0[2], a0v3 = ap0[3];
    float4 a1v0 = ap1[0], a1v1 = ap1[1], a1v2 = ap1[2], a1v3 = ap1[3];
    float a0f[16] = { a0v0.x,a0v0.y,a0v0.z,a0v0.w, a0v1.x,a0v1.y,a0v1.z,a0v1.w,
                      a0v2.x,a0v2.y,a0v2.z,a0v2.w, a0v3.x,a0v3.y,a0v3.z,a0v3.w };
    float a1f[16] = { a1v0.x,a1v0.y,a1v0.z,a1v0.w, a1v1.x,a1v1.y,a1v1.z,a1v1.w,
                      a1v2.x,a1v2.y,a1v2.z,a1v2.w, a1v3.x,a1v3.y,a1v3.z,a1v3.w };

    // ---- stage T tile (8 KB), plain coalesced copy ----
    {
        const float4* Tsrc = (const float4*)(Tg + (size_t)(b * N + m) * (H * DOUT));
        float4* Td = (float4*)Ts;
        Td[t]       = Tsrc[t];
        Td[t + 256] = Tsrc[t + 256];
    }
    __syncthreads();

    // ---- acc init = b_out for chunks c = 8k+dc  (2 f32x2 pairs per chunk) ----
    unsigned long long acc0[4][2], acc1[4][2];
    {
        const unsigned long long* bo = (const unsigned long long*)b_out;
        #pragma unroll
        for (int k = 0; k < 4; k++) {
            int c = 8 * k + dc;
            unsigned long long p0 = bo[2 * c], p1 = bo[2 * c + 1];
            acc0[k][0] = p0; acc0[k][1] = p1;
            acc1[k][0] = p0; acc1[k][1] = p1;
        }
    }

    // ---- main loop over p, FULLY unrolled ----
    const ulonglong2* TU = (const ulonglong2*)Ts;   // 16B units: [p][chunk]
    #pragma unroll
    for (int p = 0; p < H; p++) {
        unsigned long long ad0, ad1;
        DUP_F32X2(ad0, a0f[p]);
        DUP_F32X2(ad1, a1f[p]);
        #pragma unroll
        for (int k = 0; k < 4; k++) {
            ulonglong2 q = TU[p * 32 + k * 8 + dc];   // conflict-free broadcast
            FMA_F32X2(acc0[k][0], ad0, q.x, acc0[k][0]);
            FMA_F32X2(acc0[k][1], ad0, q.y, acc0[k][1]);
            FMA_F32X2(acc1[k][0], ad1, q.x, acc1[k][0]);
            FMA_F32X2(acc1[k][1], ad1, q.y, acc1[k][1]);
        }
    }

    // ---- stores: each STG.128 = contiguous 128B per row-quad ----
    size_t rb0 = (((size_t)(b * N) + r0) * MV + m) * (size_t)DOUT;
    ulonglong2* o0 = (ulonglong2*)(out + rb0);
    ulonglong2* o1 = (ulonglong2*)(out + rb0 + 4 * (size_t)MV * DOUT);
    #pragma unroll
    for (int k = 0; k < 4; k++) {
        o0[k * 8 + dc] = make_ulonglong2(acc0[k][0], acc0[k][1]);
        o1[k * 8 + dc] = make_ulonglong2(acc1[k][0], acc1[k][1]);
    }
}

// ---------------------------------------------------------------------------
extern "C" void kernel_launch(void* const* d_in, const int* in_sizes, int n_in,
                              void* d_out, int out_size)
{
    const float* feats  = (const float*)d_in[0];
    const float* gamma  = (const float*)d_in[1];
    const float* beta   = (const float*)d_in[2];
    const float* W_in   = (const float*)d_in[3];
    const float* b_in   = (const float*)d_in[4];
    const float* W_out  = (const float*)d_in[5];
    const float* b_out  = (const float*)d_in[6];
    float* out = (float*)d_out;

    float* proj; cudaGetSymbolAddress((void**)&proj, g_proj);
    float* T;    cudaGetSymbolAddress((void**)&T,    g_T);

    k_proj<<<B * N, 256>>>(feats, gamma, beta, W_in, b_in, proj);
    k_T<<<B * (MV / 8), 256>>>(proj, W_out, T);
    k_main<<<B * MV * 8, 256>>>(proj, T, b_out, out);
}

// round 5
// speedup vs baseline: 1.9827x; 1.0777x over previous
#include <cuda_runtime.h>
#include <cuda_bf16.h>
#include <cstdint>

// Problem constants
#define B    2
#define N    512
#define MV   512
#define DIN  256
#define H    16
#define DOUT 128
#define LN_EPS 1e-5f

// Scratch: proj = [B*N][32] (a = cols 0..15, bq = cols 16..31); T = [B][M][16 p][128 d]
__device__ float g_proj[B * N * 2 * H];            // 128 KB
__device__ float g_T[B * MV * H * DOUT];           // 8 MB

// packed f32x2 FMA: d = a*b + c lanewise on two fp32 packed in a 64-bit reg
#define FMA_F32X2(d_, a_, b_, c_) \
    asm("fma.rn.f32x2 %0, %1, %2, %3;" : "=l"(d_) : "l"(a_), "l"(b_), "l"(c_))

// duplicate one fp32 into both lanes of an f32x2 pack
#define DUP_F32X2(d_, f_) \
    asm("mov.b64 %0, {%1, %1};" : "=l"(d_) : "f"(f_))

// streaming 16B store (evict-first)
#define STCS_V2U64(p_, x_, y_) \
    asm volatile("st.global.cs.v2.u64 [%0], {%1, %2};" \
                 :: "l"(p_), "l"(x_), "l"(y_) : "memory")

// ---------------------------------------------------------------------------
// k_pre: fused LayerNorm + proj + T.  Grid = 128 blocks x 256 threads.
// Block handles 8 global rows r = blk*8 .. blk*8+7  (r = b*N + n).
//   smem: Wt  = W_out transposed [pq][d], rows padded to 129 (conflict-free)
//         Wins= W_in  [256][32]
//         xs  = normalized feats [8][256]
//         bqs = bq half of proj  [8][16]
// Phase A: warp w does LN of row w.
// Phase B: thread (w,lane) -> proj[row=w][col=lane] (256-FMA, 4-way split).
// Phase C: k_T body with conflict-free smem W (fixes uncoalesced W_out gather).
// ---------------------------------------------------------------------------
#define WT_FLOATS   (256 * 129)                    // 33024
#define WIN_FLOATS  (DIN * 32)                     // 8192
#define XS_FLOATS   (8 * DIN)                      // 2048
#define BQ_FLOATS   (8 * 16)                       // 128
#define PRE_SMEM_FLOATS (WT_FLOATS + WIN_FLOATS + XS_FLOATS + BQ_FLOATS)
#define PRE_SMEM_BYTES  (PRE_SMEM_FLOATS * 4)      // 173,568 B

__global__ __launch_bounds__(256) void k_pre(
    const float* __restrict__ feats, const float* __restrict__ gamma,
    const float* __restrict__ beta,  const float* __restrict__ W_in,
    const float* __restrict__ b_in,  const float* __restrict__ W_out,
    float* __restrict__ proj,        float* __restrict__ T)
{
    extern __shared__ float sm[];
    float* Wt   = sm;
    float* Wins = sm + WT_FLOATS;
    float* xs   = sm + WT_FLOATS + WIN_FLOATS;
    float* bqs  = sm + WT_FLOATS + WIN_FLOATS + XS_FLOATS;

    int t    = threadIdx.x;
    int blk  = blockIdx.x;
    int w    = t >> 5;
    int lane = t & 31;

    // ---- stage Wt = W_out^T, scalar coalesced LDG + conflict-free STS ----
    #pragma unroll 4
    for (int it = 0; it < 128; it++) {
        int idx = t + it * 256;            // 0..32767
        int d   = idx >> 8;                // 0..127
        int pq  = idx & 255;               // 0..255
        Wt[pq * 129 + d] = W_out[idx];
    }
    // ---- stage W_in (natural layout) ----
    #pragma unroll
    for (int it = 0; it < 8; it++) {
        int idx = t + it * 256;            // 2048 float4
        ((float4*)Wins)[idx] = ((const float4*)W_in)[idx];
    }

    // ---- Phase A: LN, warp per row ----
    int r = blk * 8 + w;                   // global row = b*N + n
    {
        const float4* f4 = (const float4*)(feats + (size_t)r * DIN);
        float4 va = f4[lane * 2], vb = f4[lane * 2 + 1];
        float s  = va.x + va.y + va.z + va.w + vb.x + vb.y + vb.z + vb.w;
        float s2 = va.x*va.x + va.y*va.y + va.z*va.z + va.w*va.w
                 + vb.x*vb.x + vb.y*vb.y + vb.z*vb.z + vb.w*vb.w;
        #pragma unroll
        for (int o = 16; o; o >>= 1) {
            s  += __shfl_xor_sync(0xFFFFFFFFu, s,  o);
            s2 += __shfl_xor_sync(0xFFFFFFFFu, s2, o);
        }
        float mu  = s  * (1.f / DIN);
        float var = s2 * (1.f / DIN) - mu * mu;
        float rs  = rsqrtf(var + LN_EPS);

        const float4* g4 = (const float4*)gamma;
        const float4* b4 = (const float4*)beta;
        float4 ga = g4[lane * 2], gb = g4[lane * 2 + 1];
        float4 ba = b4[lane * 2], bb = b4[lane * 2 + 1];
        float* xrow = xs + w * DIN + lane * 8;
        xrow[0] = (va.x - mu) * rs * ga.x + ba.x;
        xrow[1] = (va.y - mu) * rs * ga.y + ba.y;
        xrow[2] = (va.z - mu) * rs * ga.z + ba.z;
        xrow[3] = (va.w - mu) * rs * ga.w + ba.w;
        xrow[4] = (vb.x - mu) * rs * gb.x + bb.x;
        xrow[5] = (vb.y - mu) * rs * gb.y + bb.y;
        xrow[6] = (vb.z - mu) * rs * gb.z + bb.z;
        xrow[7] = (vb.w - mu) * rs * gb.w + bb.w;
    }
    __syncthreads();

    // ---- Phase B: proj[row=w][col=lane], 4-way split chain ----
    {
        const float* xr = xs + w * DIN;
        float a0 = 0.f, a1 = 0.f, a2 = 0.f, a3 = 0.f;
        #pragma unroll
        for (int i = 0; i < DIN; i += 4) {
            a0 = fmaf(xr[i],     Wins[(i)     * 32 + lane], a0);
            a1 = fmaf(xr[i + 1], Wins[(i + 1) * 32 + lane], a1);
            a2 = fmaf(xr[i + 2], Wins[(i + 2) * 32 + lane], a2);
            a3 = fmaf(xr[i + 3], Wins[(i + 3) * 32 + lane], a3);
        }
        float pv = b_in[lane] + ((a0 + a1) + (a2 + a3));
        proj[r * 32 + lane] = pv;
        if (lane >= 16) bqs[w * 16 + (lane - 16)] = pv;
    }
    __syncthreads();

    // ---- Phase C: T[row][p][d] = sum_q Wt[p*16+q][d] * bq[row][q] ----
    {
        int d  = t & 127;
        int ph = t >> 7;                   // 0..1
        int base_r = blk * 8;
        #pragma unroll
        for (int pi = 0; pi < 8; pi++) {
            int p = ph * 8 + pi;
            float wq[16];
            #pragma unroll
            for (int q = 0; q < 16; q++)
                wq[q] = Wt[(p * 16 + q) * 129 + d];
            #pragma unroll
            for (int mm = 0; mm < 8; mm++) {
                float acc = 0.f;
                #pragma unroll
                for (int q = 0; q < 16; q++)
                    acc = fmaf(wq[q], bqs[mm * 16 + q], acc);
                T[((size_t)(base_r + mm) * H + p) * DOUT + d] = acc;
            }
        }
    }
}

// ---------------------------------------------------------------------------
// k_main (v4 + streaming stores).
// out[b,n,m,d] = b_out[d] + sum_p a[b,n,p] * T[b,m,p,d]
// Grid = B * M * 8 n-blocks = 8192 CTAs, 256 threads, occ 2.
// Warp = 8 n-rows x 128 d.  Lane -> (rq = lane>>3 row-quad, dc = lane&7).
// Thread = rows {r0, r0+4} x 4 d-chunks {8k+dc}. Dense 128B stores,
// conflict-free broadcast LDS of T, fully unrolled p-loop (a in regs).
// ---------------------------------------------------------------------------
__global__ __launch_bounds__(256, 2) void k_main(
    const float* __restrict__ proj, const float* __restrict__ Tg,
    const float* __restrict__ b_out, float* __restrict__ out)
{
    int job  = blockIdx.x;          // 0..8191
    int b    = job >> 12;
    int m    = (job >> 3) & 511;
    int n0   = (job & 7) * 64;
    int t    = threadIdx.x;
    int w    = t >> 5;
    int lane = t & 31;
    int rq   = lane >> 3;           // 0..3
    int dc   = lane & 7;            // 0..7

    __shared__ __align__(16) float Ts[H * DOUT];    // 8 KB, natural [p][d]

    int r0 = n0 + w * 8 + rq;       // rows r0 and r0+4

    // ---- load a (rows r0, r0+4), fully register-resident ----
    const float4* ap0 = (const float4*)(proj + (size_t)(b * N + r0) * 32);
    const float4* ap1 = (const float4*)(proj + (size_t)(b * N + r0 + 4) * 32);
    float4 a0v0 = ap0[0], a0v1 = ap0[1], a0v2 = ap0[2], a0v3 = ap0[3];
    float4 a1v0 = ap1[0], a1v1 = ap1[1], a1v2 = ap1[2], a1v3 = ap1[3];
    float a0f[16] = { a0v0.x,a0v0.y,a0v0.z,a0v0.w, a0v1.x,a0v1.y,a0v1.z,a0v1.w,
                      a0v2.x,a0v2.y,a0v2.z,a0v2.w, a0v3.x,a0v3.y,a0v3.z,a0v3.w };
    float a1f[16] = { a1v0.x,a1v0.y,a1v0.z,a1v0.w, a1v1.x,a1v1.y,a1v1.z,a1v1.w,
                      a1v2.x,a1v2.y,a1v2.z,a1v2.w, a1v3.x,a1v3.y,a1v3.z,a1v3.w };

    // ---- stage T tile (8 KB), plain coalesced copy ----
    {
        const float4* Tsrc = (const float4*)(Tg + (size_t)(b * N + m) * (H * DOUT));
        float4* Td = (float4*)Ts;
        Td[t]       = Tsrc[t];
        Td[t + 256] = Tsrc[t + 256];
    }
    __syncthreads();

    // ---- acc init = b_out for chunks c = 8k+dc ----
    unsigned long long acc0[4][2], acc1[4][2];
    {
        const unsigned long long* bo = (const unsigned long long*)b_out;
        #pragma unroll
        for (int k = 0; k < 4; k++) {
            int c = 8 * k + dc;
            unsigned long long p0 = bo[2 * c], p1 = bo[2 * c + 1];
            acc0[k][0] = p0; acc0[k][1] = p1;
            acc1[k][0] = p0; acc1[k][1] = p1;
        }
    }

    // ---- main loop over p, FULLY unrolled ----
    const ulonglong2* TU = (const ulonglong2*)Ts;   // 16B units: [p][chunk]
    #pragma unroll
    for (int p = 0; p < H; p++) {
        unsigned long long ad0, ad1;
        DUP_F32X2(ad0, a0f[p]);
        DUP_F32X2(ad1, a1f[p]);
        #pragma unroll
        for (int k = 0; k < 4; k++) {
            ulonglong2 q = TU[p * 32 + k * 8 + dc];   // conflict-free broadcast
            FMA_F32X2(acc0[k][0], ad0, q.x, acc0[k][0]);
            FMA_F32X2(acc0[k][1], ad0, q.y, acc0[k][1]);
            FMA_F32X2(acc1[k][0], ad1, q.x, acc1[k][0]);
            FMA_F32X2(acc1[k][1], ad1, q.y, acc1[k][1]);
        }
    }

    // ---- streaming stores: each STG = dense 128B per row-quad ----
    size_t rb0 = (((size_t)(b * N) + r0) * MV + m) * (size_t)DOUT;
    float* o0 = out + rb0;
    float* o1 = out + rb0 + 4 * (size_t)MV * DOUT;
    #pragma unroll
    for (int k = 0; k < 4; k++) {
        STCS_V2U64(o0 + (k * 8 + dc) * 4, acc0[k][0], acc0[k][1]);
        STCS_V2U64(o1 + (k * 8 + dc) * 4, acc1[k][0], acc1[k][1]);
    }
}

// ---------------------------------------------------------------------------
extern "C" void kernel_launch(void* const* d_in, const int* in_sizes, int n_in,
                              void* d_out, int out_size)
{
    const float* feats  = (const float*)d_in[0];
    const float* gamma  = (const float*)d_in[1];
    const float* beta   = (const float*)d_in[2];
    const float* W_in   = (const float*)d_in[3];
    const float* b_in   = (const float*)d_in[4];
    const float* W_out  = (const float*)d_in[5];
    const float* b_out  = (const float*)d_in[6];
    float* out = (float*)d_out;

    float* proj; cudaGetSymbolAddress((void**)&proj, g_proj);
    float* T;    cudaGetSymbolAddress((void**)&T,    g_T);

    cudaFuncSetAttribute(k_pre, cudaFuncAttributeMaxDynamicSharedMemorySize,
                         PRE_SMEM_BYTES);

    k_pre<<<(B * N) / 8, 256, PRE_SMEM_BYTES>>>(feats, gamma, beta, W_in, b_in,
                                                W_out, proj, T);
    k_main<<<B * MV * 8, 256>>>(proj, T, b_out, out);
}

// round 6
// speedup vs baseline: 2.5002x; 1.2610x over previous
#include <cuda_runtime.h>
#include <cuda_bf16.h>
#include <cstdint>

// Problem constants
#define B    2
#define N    512
#define MV   512
#define DIN  256
#define H    16
#define DOUT 128
#define LN_EPS 1e-5f

__device__ float g_proj[B * N * 2 * H];            // 128 KB
__device__ float g_T[B * MV * H * DOUT];           // 8 MB

#define FMA_F32X2(d_, a_, b_, c_) \
    asm("fma.rn.f32x2 %0, %1, %2, %3;" : "=l"(d_) : "l"(a_), "l"(b_), "l"(c_))

#define DUP_F32X2(d_, f_) \
    asm("mov.b64 %0, {%1, %1};" : "=l"(d_) : "f"(f_))

#define STCS_V2U64(p_, x_, y_) \
    asm volatile("st.global.cs.v2.u64 [%0], {%1, %2};" \
                 :: "l"(p_), "l"(x_), "l"(y_) : "memory")

// ---------------------------------------------------------------------------
// k_pre: fused LayerNorm + proj + T.  Grid = 128 blocks x 256 threads.
// (unchanged from R5 — ~10us, not the bottleneck)
// ---------------------------------------------------------------------------
#define WT_FLOATS   (256 * 129)
#define WIN_FLOATS  (DIN * 32)
#define XS_FLOATS   (8 * DIN)
#define BQ_FLOATS   (8 * 16)
#define PRE_SMEM_FLOATS (WT_FLOATS + WIN_FLOATS + XS_FLOATS + BQ_FLOATS)
#define PRE_SMEM_BYTES  (PRE_SMEM_FLOATS * 4)

__global__ __launch_bounds__(256) void k_pre(
    const float* __restrict__ feats, const float* __restrict__ gamma,
    const float* __restrict__ beta,  const float* __restrict__ W_in,
    const float* __restrict__ b_in,  const float* __restrict__ W_out,
    float* __restrict__ proj,        float* __restrict__ T)
{
    extern __shared__ float sm[];
    float* Wt   = sm;
    float* Wins = sm + WT_FLOATS;
    float* xs   = sm + WT_FLOATS + WIN_FLOATS;
    float* bqs  = sm + WT_FLOATS + WIN_FLOATS + XS_FLOATS;

    int t    = threadIdx.x;
    int blk  = blockIdx.x;
    int w    = t >> 5;
    int lane = t & 31;

    #pragma unroll 4
    for (int it = 0; it < 128; it++) {
        int idx = t + it * 256;
        int d   = idx >> 8;
        int pq  = idx & 255;
        Wt[pq * 129 + d] = W_out[idx];
    }
    #pragma unroll
    for (int it = 0; it < 8; it++) {
        int idx = t + it * 256;
        ((float4*)Wins)[idx] = ((const float4*)W_in)[idx];
    }

    int r = blk * 8 + w;
    {
        const float4* f4 = (const float4*)(feats + (size_t)r * DIN);
        float4 va = f4[lane * 2], vb = f4[lane * 2 + 1];
        float s  = va.x + va.y + va.z + va.w + vb.x + vb.y + vb.z + vb.w;
        float s2 = va.x*va.x + va.y*va.y + va.z*va.z + va.w*va.w
                 + vb.x*vb.x + vb.y*vb.y + vb.z*vb.z + vb.w*vb.w;
        #pragma unroll
        for (int o = 16; o; o >>= 1) {
            s  += __shfl_xor_sync(0xFFFFFFFFu, s,  o);
            s2 += __shfl_xor_sync(0xFFFFFFFFu, s2, o);
        }
        float mu  = s  * (1.f / DIN);
        float var = s2 * (1.f / DIN) - mu * mu;
        float rs  = rsqrtf(var + LN_EPS);

        const float4* g4 = (const float4*)gamma;
        const float4* b4 = (const float4*)beta;
        float4 ga = g4[lane * 2], gb = g4[lane * 2 + 1];
        float4 ba = b4[lane * 2], bb = b4[lane * 2 + 1];
        float* xrow = xs + w * DIN + lane * 8;
        xrow[0] = (va.x - mu) * rs * ga.x + ba.x;
        xrow[1] = (va.y - mu) * rs * ga.y + ba.y;
        xrow[2] = (va.z - mu) * rs * ga.z + ba.z;
        xrow[3] = (va.w - mu) * rs * ga.w + ba.w;
        xrow[4] = (vb.x - mu) * rs * gb.x + bb.x;
        xrow[5] = (vb.y - mu) * rs * gb.y + bb.y;
        xrow[6] = (vb.z - mu) * rs * gb.z + bb.z;
        xrow[7] = (vb.w - mu) * rs * gb.w + bb.w;
    }
    __syncthreads();

    {
        const float* xr = xs + w * DIN;
        float a0 = 0.f, a1 = 0.f, a2 = 0.f, a3 = 0.f;
        #pragma unroll
        for (int i = 0; i < DIN; i += 4) {
            a0 = fmaf(xr[i],     Wins[(i)     * 32 + lane], a0);
            a1 = fmaf(xr[i + 1], Wins[(i + 1) * 32 + lane], a1);
            a2 = fmaf(xr[i + 2], Wins[(i + 2) * 32 + lane], a2);
            a3 = fmaf(xr[i + 3], Wins[(i + 3) * 32 + lane], a3);
        }
        float pv = b_in[lane] + ((a0 + a1) + (a2 + a3));
        proj[r * 32 + lane] = pv;
        if (lane >= 16) bqs[w * 16 + (lane - 16)] = pv;
    }
    __syncthreads();

    {
        int d  = t & 127;
        int ph = t >> 7;
        int base_r = blk * 8;
        #pragma unroll
        for (int pi = 0; pi < 8; pi++) {
            int p = ph * 8 + pi;
            float wq[16];
            #pragma unroll
            for (int q = 0; q < 16; q++)
                wq[q] = Wt[(p * 16 + q) * 129 + d];
            #pragma unroll
            for (int mm = 0; mm < 8; mm++) {
                float acc = 0.f;
                #pragma unroll
                for (int q = 0; q < 16; q++)
                    acc = fmaf(wq[q], bqs[mm * 16 + q], acc);
                T[((size_t)(base_r + mm) * H + p) * DOUT + d] = acc;
            }
        }
    }
}

// ---------------------------------------------------------------------------
// k_main v5: out[b,n,m,d] = b_out[d] + sum_p a[b,n,p] * T[b,m,p,d]
// Grid = B * M * 4 n-blocks = 4096 CTAs, 256 threads, occ 2.
// CTA covers 128 n-rows.  Warp w = rows w*16..w*16+15 x all 128 d.
// Thread = 16 rows x ONE 16B d-chunk (d = lane*4 .. lane*4+3).
// Per p per warp: 1 LDS.128 T (512B distinct, 4 wf) + 4 broadcast LDS.128 a
// (4 wf) + 16 DUP (ALU) + 32 FFMA2  ->  FMA-bound, L1 wavefronts ~1/3 of v4.
// ---------------------------------------------------------------------------
__global__ __launch_bounds__(256, 2) void k_main(
    const float* __restrict__ proj, const float* __restrict__ Tg,
    const float* __restrict__ b_out, float* __restrict__ out)
{
    int job  = blockIdx.x;          // 0..4095
    int b    = job >> 11;
    int m    = (job >> 2) & 511;
    int n0   = (job & 3) * 128;
    int t    = threadIdx.x;
    int w    = t >> 5;              // warp: rows w*16 .. w*16+15
    int lane = t & 31;              // chunk: d = lane*4 .. +3

    __shared__ __align__(16) float Ts[H * DOUT];   // 8 KB, natural [p][d]
    __shared__ __align__(16) float As[H * 128];    // 8 KB, [p][row]

    // ---- stage T tile (8 KB) ----
    {
        const float4* Tsrc = (const float4*)(Tg + (size_t)(b * N + m) * (H * DOUT));
        float4* Td = (float4*)Ts;
        Td[t]       = Tsrc[t];
        Td[t + 256] = Tsrc[t + 256];
    }
    // ---- stage a transposed: As[p][row], row = CTA-local 0..127 ----
    {
        int row  = t & 127;
        int half = t >> 7;                       // 0..1 -> p = half*8..+7
        const float4* pr = (const float4*)
            (proj + (size_t)(b * N + n0 + row) * 32 + half * 8);
        float4 v0 = pr[0], v1 = pr[1];
        As[(half * 8 + 0) * 128 + row] = v0.x;
        As[(half * 8 + 1) * 128 + row] = v0.y;
        As[(half * 8 + 2) * 128 + row] = v0.z;
        As[(half * 8 + 3) * 128 + row] = v0.w;
        As[(half * 8 + 4) * 128 + row] = v1.x;
        As[(half * 8 + 5) * 128 + row] = v1.y;
        As[(half * 8 + 6) * 128 + row] = v1.z;
        As[(half * 8 + 7) * 128 + row] = v1.w;
    }
    __syncthreads();

    // ---- acc init = b_out[lane*4 .. +3] for all 16 rows ----
    unsigned long long acc[16][2];
    {
        const unsigned long long* bo = (const unsigned long long*)b_out;
        unsigned long long p0 = bo[2 * lane], p1 = bo[2 * lane + 1];
        #pragma unroll
        for (int j = 0; j < 16; j++) { acc[j][0] = p0; acc[j][1] = p1; }
    }

    // ---- main loop over p ----
    const ulonglong2* TU = (const ulonglong2*)Ts;   // 16B units [p][chunk]
    #pragma unroll
    for (int p = 0; p < H; p++) {
        ulonglong2 q = TU[p * 32 + lane];           // 512B distinct per warp
        const float4* af = (const float4*)(As + p * 128 + w * 16);
        float4 A0 = af[0], A1 = af[1], A2 = af[2], A3 = af[3];  // broadcast
        float a16[16] = { A0.x,A0.y,A0.z,A0.w, A1.x,A1.y,A1.z,A1.w,
                          A2.x,A2.y,A2.z,A2.w, A3.x,A3.y,A3.z,A3.w };
        #pragma unroll
        for (int j = 0; j < 16; j++) {
            unsigned long long ad;
            DUP_F32X2(ad, a16[j]);
            FMA_F32X2(acc[j][0], ad, q.x, acc[j][0]);
            FMA_F32X2(acc[j][1], ad, q.y, acc[j][1]);
        }
    }

    // ---- streaming stores: per row, warp writes 512B contiguous ----
    size_t rowstride = (size_t)MV * DOUT;
    float* base = out + (((size_t)(b * N) + n0 + w * 16) * MV + m) * DOUT
                      + lane * 4;
    #pragma unroll
    for (int j = 0; j < 16; j++) {
        STCS_V2U64(base + (size_t)j * rowstride, acc[j][0], acc[j][1]);
    }
}

// ---------------------------------------------------------------------------
extern "C" void kernel_launch(void* const* d_in, const int* in_sizes, int n_in,
                              void* d_out, int out_size)
{
    const float* feats  = (const float*)d_in[0];
    const float* gamma  = (const float*)d_in[1];
    const float* beta   = (const float*)d_in[2];
    const float* W_in   = (const float*)d_in[3];
    const float* b_in   = (const float*)d_in[4];
    const float* W_out  = (const float*)d_in[5];
    const float* b_out  = (const float*)d_in[6];
    float* out = (float*)d_out;

    float* proj; cudaGetSymbolAddress((void**)&proj, g_proj);
    float* T;    cudaGetSymbolAddress((void**)&T,    g_T);

    cudaFuncSetAttribute(k_pre, cudaFuncAttributeMaxDynamicSharedMemorySize,
                         PRE_SMEM_BYTES);

    k_pre<<<(B * N) / 8, 256, PRE_SMEM_BYTES>>>(feats, gamma, beta, W_in, b_in,
                                                W_out, proj, T);
    k_main<<<B * MV * 4, 256>>>(proj, T, b_out, out);
}

// round 7
// speedup vs baseline: 3.2069x; 1.2826x over previous
#include <cuda_runtime.h>
#include <cuda_bf16.h>
#include <cstdint>

// Problem constants
#define B    2
#define N    512
#define MV   512
#define DIN  256
#define H    16
#define DOUT 128
#define LN_EPS 1e-5f

__device__ float g_proj[B * N * 2 * H];            // 128 KB
__device__ float g_T[B * MV * H * DOUT];           // 8 MB

#define FMA_F32X2(d_, a_, b_, c_) \
    asm("fma.rn.f32x2 %0, %1, %2, %3;" : "=l"(d_) : "l"(a_), "l"(b_), "l"(c_))

#define DUP_F32X2(d_, f_) \
    asm("mov.b64 %0, {%1, %1};" : "=l"(d_) : "f"(f_))

#define STCS_V2U64(p_, x_, y_) \
    asm volatile("st.global.cs.v2.u64 [%0], {%1, %2};" \
                 :: "l"(p_), "l"(x_), "l"(y_) : "memory")

// ---------------------------------------------------------------------------
// k_pre: fused LayerNorm + proj + T.  Grid = 128 blocks x 256 threads.
// (unchanged from R6)
// ---------------------------------------------------------------------------
#define WT_FLOATS   (256 * 129)
#define WIN_FLOATS  (DIN * 32)
#define XS_FLOATS   (8 * DIN)
#define BQ_FLOATS   (8 * 16)
#define PRE_SMEM_FLOATS (WT_FLOATS + WIN_FLOATS + XS_FLOATS + BQ_FLOATS)
#define PRE_SMEM_BYTES  (PRE_SMEM_FLOATS * 4)

__global__ __launch_bounds__(256) void k_pre(
    const float* __restrict__ feats, const float* __restrict__ gamma,
    const float* __restrict__ beta,  const float* __restrict__ W_in,
    const float* __restrict__ b_in,  const float* __restrict__ W_out,
    float* __restrict__ proj,        float* __restrict__ T)
{
    extern __shared__ float sm[];
    float* Wt   = sm;
    float* Wins = sm + WT_FLOATS;
    float* xs   = sm + WT_FLOATS + WIN_FLOATS;
    float* bqs  = sm + WT_FLOATS + WIN_FLOATS + XS_FLOATS;

    int t    = threadIdx.x;
    int blk  = blockIdx.x;
    int w    = t >> 5;
    int lane = t & 31;

    #pragma unroll 4
    for (int it = 0; it < 128; it++) {
        int idx = t + it * 256;
        int d   = idx >> 8;
        int pq  = idx & 255;
        Wt[pq * 129 + d] = W_out[idx];
    }
    #pragma unroll
    for (int it = 0; it < 8; it++) {
        int idx = t + it * 256;
        ((float4*)Wins)[idx] = ((const float4*)W_in)[idx];
    }

    int r = blk * 8 + w;
    {
        const float4* f4 = (const float4*)(feats + (size_t)r * DIN);
        float4 va = f4[lane * 2], vb = f4[lane * 2 + 1];
        float s  = va.x + va.y + va.z + va.w + vb.x + vb.y + vb.z + vb.w;
        float s2 = va.x*va.x + va.y*va.y + va.z*va.z + va.w*va.w
                 + vb.x*vb.x + vb.y*vb.y + vb.z*vb.z + vb.w*vb.w;
        #pragma unroll
        for (int o = 16; o; o >>= 1) {
            s  += __shfl_xor_sync(0xFFFFFFFFu, s,  o);
            s2 += __shfl_xor_sync(0xFFFFFFFFu, s2, o);
        }
        float mu  = s  * (1.f / DIN);
        float var = s2 * (1.f / DIN) - mu * mu;
        float rs  = rsqrtf(var + LN_EPS);

        const float4* g4 = (const float4*)gamma;
        const float4* b4 = (const float4*)beta;
        float4 ga = g4[lane * 2], gb = g4[lane * 2 + 1];
        float4 ba = b4[lane * 2], bb = b4[lane * 2 + 1];
        float* xrow = xs + w * DIN + lane * 8;
        xrow[0] = (va.x - mu) * rs * ga.x + ba.x;
        xrow[1] = (va.y - mu) * rs * ga.y + ba.y;
        xrow[2] = (va.z - mu) * rs * ga.z + ba.z;
        xrow[3] = (va.w - mu) * rs * ga.w + ba.w;
        xrow[4] = (vb.x - mu) * rs * gb.x + bb.x;
        xrow[5] = (vb.y - mu) * rs * gb.y + bb.y;
        xrow[6] = (vb.z - mu) * rs * gb.z + bb.z;
        xrow[7] = (vb.w - mu) * rs * gb.w + bb.w;
    }
    __syncthreads();

    {
        const float* xr = xs + w * DIN;
        float a0 = 0.f, a1 = 0.f, a2 = 0.f, a3 = 0.f;
        #pragma unroll
        for (int i = 0; i < DIN; i += 4) {
            a0 = fmaf(xr[i],     Wins[(i)     * 32 + lane], a0);
            a1 = fmaf(xr[i + 1], Wins[(i + 1) * 32 + lane], a1);
            a2 = fmaf(xr[i + 2], Wins[(i + 2) * 32 + lane], a2);
            a3 = fmaf(xr[i + 3], Wins[(i + 3) * 32 + lane], a3);
        }
        float pv = b_in[lane] + ((a0 + a1) + (a2 + a3));
        proj[r * 32 + lane] = pv;
        if (lane >= 16) bqs[w * 16 + (lane - 16)] = pv;
    }
    __syncthreads();

    {
        int d  = t & 127;
        int ph = t >> 7;
        int base_r = blk * 8;
        #pragma unroll
        for (int pi = 0; pi < 8; pi++) {
            int p = ph * 8 + pi;
            float wq[16];
            #pragma unroll
            for (int q = 0; q < 16; q++)
                wq[q] = Wt[(p * 16 + q) * 129 + d];
            #pragma unroll
            for (int mm = 0; mm < 8; mm++) {
                float acc = 0.f;
                #pragma unroll
                for (int q = 0; q < 16; q++)
                    acc = fmaf(wq[q], bqs[mm * 16 + q], acc);
                T[((size_t)(base_r + mm) * H + p) * DOUT + d] = acc;
            }
        }
    }
}

// ---------------------------------------------------------------------------
// k_main v6: out[b,n,m,d] = b_out[d] + sum_p a[b,n,p] * T[b,m,p,d]
// Grid = B * M = 1024 CTAs, 256 threads (8 warps), occ 2.
// CTA covers ALL 512 n-rows for one (b,m).  Warp w = rows w*64..w*64+63.
// Thread = ONE d-chunk (d = lane*4..+3) x 64 rows.
// T for all 16 p hoisted into 64 REGISTERS once per CTA (zero T-LDS in the
// row loop).  Per row: 4 broadcast LDS.128 (a) + 16 DUP + 32 FFMA2 + 1 STG.
// ---------------------------------------------------------------------------
__global__ __launch_bounds__(256, 2) void k_main(
    const float* __restrict__ proj, const float* __restrict__ Tg,
    const float* __restrict__ b_out, float* __restrict__ out)
{
    int b    = blockIdx.x >> 9;
    int m    = blockIdx.x & 511;
    int t    = threadIdx.x;
    int w    = t >> 5;              // warp -> rows w*64 .. w*64+63
    int lane = t & 31;              // chunk: d = lane*4 .. +3

    __shared__ __align__(16) float Ts[H * DOUT];   // 8 KB  [p][d]
    __shared__ __align__(16) float As[N * H];      // 32 KB [row][p]

    // ---- stage T tile (8 KB) ----
    {
        const float4* Tsrc = (const float4*)(Tg + (size_t)(b * N + m) * (H * DOUT));
        float4* Td = (float4*)Ts;
        Td[t]       = Tsrc[t];
        Td[t + 256] = Tsrc[t + 256];
    }
    // ---- stage a for all 512 rows: As[row][p], p = 0..15 ----
    {
        const float4* psrc = (const float4*)(proj + (size_t)b * N * 32);
        float4* Ad = (float4*)As;
        #pragma unroll
        for (int it = 0; it < 8; it++) {
            int idx = t + it * 256;        // 0..2047
            int row = idx >> 2;
            int q4  = idx & 3;             // which float4 of the a-half
            Ad[idx] = psrc[row * 8 + q4];  // proj row = 8 float4; a = first 4
        }
    }
    __syncthreads();

    // ---- hoist T into registers: Tp[p] = 16B chunk for this lane ----
    unsigned long long Tp[H][2];
    {
        const ulonglong2* TU = (const ulonglong2*)Ts;
        #pragma unroll
        for (int p = 0; p < H; p++) {
            ulonglong2 q = TU[p * 32 + lane];
            Tp[p][0] = q.x; Tp[p][1] = q.y;
        }
    }

    // ---- bias pack for this chunk ----
    unsigned long long bo0, bo1;
    {
        const unsigned long long* bo = (const unsigned long long*)b_out;
        bo0 = bo[2 * lane]; bo1 = bo[2 * lane + 1];
    }

    // ---- stream 64 rows: batches of 4, outer loop NOT unrolled ----
    size_t rowstride = (size_t)MV * DOUT;
    float* obase = out + (((size_t)(b * N) + w * 64) * MV + m) * DOUT + lane * 4;

    #pragma unroll 1
    for (int jb = 0; jb < 64; jb += 4) {
        unsigned long long acc[4][2];
        #pragma unroll
        for (int j = 0; j < 4; j++) { acc[j][0] = bo0; acc[j][1] = bo1; }

        #pragma unroll
        for (int j = 0; j < 4; j++) {
            int row = w * 64 + jb + j;
            const float4* ar = (const float4*)(As + row * H);
            float4 A0 = ar[0], A1 = ar[1], A2 = ar[2], A3 = ar[3];
            float a16[16] = { A0.x,A0.y,A0.z,A0.w, A1.x,A1.y,A1.z,A1.w,
                              A2.x,A2.y,A2.z,A2.w, A3.x,A3.y,A3.z,A3.w };
            #pragma unroll
            for (int p = 0; p < H; p++) {
                unsigned long long ad;
                DUP_F32X2(ad, a16[p]);
                FMA_F32X2(acc[j][0], ad, Tp[p][0], acc[j][0]);
                FMA_F32X2(acc[j][1], ad, Tp[p][1], acc[j][1]);
            }
        }

        float* op = obase + (size_t)jb * rowstride;
        #pragma unroll
        for (int j = 0; j < 4; j++)
            STCS_V2U64(op + (size_t)j * rowstride, acc[j][0], acc[j][1]);
    }
}

// ---------------------------------------------------------------------------
extern "C" void kernel_launch(void* const* d_in, const int* in_sizes, int n_in,
                              void* d_out, int out_size)
{
    const float* feats  = (const float*)d_in[0];
    const float* gamma  = (const float*)d_in[1];
    const float* beta   = (const float*)d_in[2];
    const float* W_in   = (const float*)d_in[3];
    const float* b_in   = (const float*)d_in[4];
    const float* W_out  = (const float*)d_in[5];
    const float* b_out  = (const float*)d_in[6];
    float* out = (float*)d_out;

    float* proj; cudaGetSymbolAddress((void**)&proj, g_proj);
    float* T;    cudaGetSymbolAddress((void**)&T,    g_T);

    cudaFuncSetAttribute(k_pre, cudaFuncAttributeMaxDynamicSharedMemorySize,
                         PRE_SMEM_BYTES);

    k_pre<<<(B * N) / 8, 256, PRE_SMEM_BYTES>>>(feats, gamma, beta, W_in, b_in,
                                                W_out, proj, T);
    k_main<<<B * MV, 256>>>(proj, T, b_out, out);
}

// round 8
// speedup vs baseline: 3.2103x; 1.0011x over previous
#include <cuda_runtime.h>
#include <cuda_bf16.h>
#include <cstdint>

// Problem constants
#define B    2
#define N    512
#define MV   512
#define DIN  256
#define H    16
#define DOUT 128
#define LN_EPS 1e-5f

__device__ float g_proj[B * N * 2 * H];            // 128 KB
__device__ float g_T[B * MV * H * DOUT];           // 8 MB
__device__ float g_Wt[256 * DOUT];                 // 128 KB, W_out^T [pq][d]

#define FMA_F32X2(d_, a_, b_, c_) \
    asm("fma.rn.f32x2 %0, %1, %2, %3;" : "=l"(d_) : "l"(a_), "l"(b_), "l"(c_))

#define DUP_F32X2(d_, f_) \
    asm("mov.b64 %0, {%1, %1};" : "=l"(d_) : "f"(f_))

#define STCS_V2U64(p_, x_, y_) \
    asm volatile("st.global.cs.v2.u64 [%0], {%1, %2};" \
                 :: "l"(p_), "l"(x_), "l"(y_) : "memory")

// ---------------------------------------------------------------------------
// k_wt: transpose W_out [128 d][256 pq] -> Wt_g [256 pq][128 d].  Once.
// Grid = 128 CTAs (one per d row), 256 threads (one per pq).
// ---------------------------------------------------------------------------
__global__ __launch_bounds__(256) void k_wt(
    const float* __restrict__ W_out, float* __restrict__ Wt)
{
    int d  = blockIdx.x;
    int pq = threadIdx.x;
    Wt[pq * DOUT + d] = W_out[d * 256 + pq];
}

// ---------------------------------------------------------------------------
// k_pre v2: fused LayerNorm + proj + T.  Grid = 128 blocks x 256 threads.
// Block handles 8 global rows r = blk*8 .. blk*8+7  (r = b*N + n).
// Phase A: warp w does LN of row w (into smem xs).
// Phase B: thread (w,lane) -> proj[row=w][col=lane] from smem W_in.
// Phase C: T[row][p][d] = sum_q Wt_g[(p*16+q)][d] * bq[row][q]
//          -- Wt_g reads coalesced across lanes, L1-resident.
// ---------------------------------------------------------------------------
__global__ __launch_bounds__(256) void k_pre(
    const float* __restrict__ feats, const float* __restrict__ gamma,
    const float* __restrict__ beta,  const float* __restrict__ W_in,
    const float* __restrict__ b_in,  const float* __restrict__ Wt,
    float* __restrict__ proj,        float* __restrict__ T)
{
    __shared__ __align__(16) float Wins[DIN * 32];   // 32 KB
    __shared__ __align__(16) float xs[8][DIN];       // 8 KB
    __shared__ float bqs[8][16];

    int t    = threadIdx.x;
    int blk  = blockIdx.x;
    int w    = t >> 5;
    int lane = t & 31;

    // ---- stage W_in (coalesced float4) ----
    #pragma unroll
    for (int it = 0; it < 8; it++) {
        int idx = t + it * 256;
        ((float4*)Wins)[idx] = ((const float4*)W_in)[idx];
    }

    // ---- Phase A: LN, warp per row ----
    int r = blk * 8 + w;
    {
        const float4* f4 = (const float4*)(feats + (size_t)r * DIN);
        float4 va = f4[lane * 2], vb = f4[lane * 2 + 1];
        float s  = va.x + va.y + va.z + va.w + vb.x + vb.y + vb.z + vb.w;
        float s2 = va.x*va.x + va.y*va.y + va.z*va.z + va.w*va.w
                 + vb.x*vb.x + vb.y*vb.y + vb.z*vb.z + vb.w*vb.w;
        #pragma unroll
        for (int o = 16; o; o >>= 1) {
            s  += __shfl_xor_sync(0xFFFFFFFFu, s,  o);
            s2 += __shfl_xor_sync(0xFFFFFFFFu, s2, o);
        }
        float mu  = s  * (1.f / DIN);
        float var = s2 * (1.f / DIN) - mu * mu;
        float rs  = rsqrtf(var + LN_EPS);

        const float4* g4 = (const float4*)gamma;
        const float4* b4 = (const float4*)beta;
        float4 ga = g4[lane * 2], gb = g4[lane * 2 + 1];
        float4 ba = b4[lane * 2], bb = b4[lane * 2 + 1];
        float* xrow = xs[w] + lane * 8;
        xrow[0] = (va.x - mu) * rs * ga.x + ba.x;
        xrow[1] = (va.y - mu) * rs * ga.y + ba.y;
        xrow[2] = (va.z - mu) * rs * ga.z + ba.z;
        xrow[3] = (va.w - mu) * rs * ga.w + ba.w;
        xrow[4] = (vb.x - mu) * rs * gb.x + bb.x;
        xrow[5] = (vb.y - mu) * rs * gb.y + bb.y;
        xrow[6] = (vb.z - mu) * rs * gb.z + bb.z;
        xrow[7] = (vb.w - mu) * rs * gb.w + bb.w;
    }
    __syncthreads();

    // ---- Phase B: proj[row=w][col=lane], 4-way split chain ----
    {
        const float* xr = xs[w];
        float a0 = 0.f, a1 = 0.f, a2 = 0.f, a3 = 0.f;
        #pragma unroll
        for (int i = 0; i < DIN; i += 4) {
            a0 = fmaf(xr[i],     Wins[(i)     * 32 + lane], a0);
            a1 = fmaf(xr[i + 1], Wins[(i + 1) * 32 + lane], a1);
            a2 = fmaf(xr[i + 2], Wins[(i + 2) * 32 + lane], a2);
            a3 = fmaf(xr[i + 3], Wins[(i + 3) * 32 + lane], a3);
        }
        float pv = b_in[lane] + ((a0 + a1) + (a2 + a3));
        proj[r * 32 + lane] = pv;
        if (lane >= 16) bqs[w][lane - 16] = pv;
    }
    __syncthreads();

    // ---- Phase C: T from global Wt (coalesced, L1-hot) ----
    {
        int d  = t & 127;
        int ph = t >> 7;
        int base_r = blk * 8;
        #pragma unroll
        for (int pi = 0; pi < 8; pi++) {
            int p = ph * 8 + pi;
            float wq[16];
            #pragma unroll
            for (int q = 0; q < 16; q++)
                wq[q] = Wt[(p * 16 + q) * DOUT + d];
            #pragma unroll
            for (int mm = 0; mm < 8; mm++) {
                float acc = 0.f;
                #pragma unroll
                for (int q = 0; q < 16; q++)
                    acc = fmaf(wq[q], bqs[mm][q], acc);
                T[((size_t)(base_r + mm) * H + p) * DOUT + d] = acc;
            }
        }
    }
}

// ---------------------------------------------------------------------------
// k_main v6.1: out[b,n,m,d] = b_out[d] + sum_p a[b,n,p] * T[b,m,p,d]
// Grid = B * M * 2 = 2048 CTAs, 256 threads (8 warps), occ 2.
// CTA covers 256 n-rows for one (b,m).  Warp w = rows n0 + w*32 .. +31.
// Thread = ONE d-chunk (d = lane*4..+3) x 32 rows.
// T for all 16 p hoisted into 64 REGISTERS once per CTA.
// Per row: 4 broadcast LDS.128 (a) + 16 DUP + 32 FFMA2 + 1 STG.
// ---------------------------------------------------------------------------
__global__ __launch_bounds__(256, 2) void k_main(
    const float* __restrict__ proj, const float* __restrict__ Tg,
    const float* __restrict__ b_out, float* __restrict__ out)
{
    int b    = blockIdx.x >> 10;
    int m    = (blockIdx.x >> 1) & 511;
    int n0   = (blockIdx.x & 1) * 256;
    int t    = threadIdx.x;
    int w    = t >> 5;              // warp -> rows n0 + w*32 .. +31
    int lane = t & 31;              // chunk: d = lane*4 .. +3

    __shared__ __align__(16) float Ts[H * DOUT];     // 8 KB  [p][d]
    __shared__ __align__(16) float As[256 * H];      // 16 KB [row][p]

    // ---- stage T tile (8 KB) ----
    {
        const float4* Tsrc = (const float4*)(Tg + (size_t)(b * N + m) * (H * DOUT));
        float4* Td = (float4*)Ts;
        Td[t]       = Tsrc[t];
        Td[t + 256] = Tsrc[t + 256];
    }
    // ---- stage a for 256 rows: As[row][p] ----
    {
        const float4* psrc = (const float4*)(proj + (size_t)(b * N + n0) * 32);
        float4* Ad = (float4*)As;
        #pragma unroll
        for (int it = 0; it < 4; it++) {
            int idx = t + it * 256;        // 0..1023
            int row = idx >> 2;
            int q4  = idx & 3;
            Ad[idx] = psrc[row * 8 + q4];  // a = first 4 float4 of proj row
        }
    }
    __syncthreads();

    // ---- hoist T into registers: Tp[p] = 16B chunk for this lane ----
    unsigned long long Tp[H][2];
    {
        const ulonglong2* TU = (const ulonglong2*)Ts;
        #pragma unroll
        for (int p = 0; p < H; p++) {
            ulonglong2 q = TU[p * 32 + lane];
            Tp[p][0] = q.x; Tp[p][1] = q.y;
        }
    }

    // ---- bias pack for this chunk ----
    unsigned long long bo0, bo1;
    {
        const unsigned long long* bo = (const unsigned long long*)b_out;
        bo0 = bo[2 * lane]; bo1 = bo[2 * lane + 1];
    }

    // ---- stream 32 rows: batches of 4 ----
    size_t rowstride = (size_t)MV * DOUT;
    float* obase = out + (((size_t)(b * N) + n0 + w * 32) * MV + m) * DOUT
                       + lane * 4;

    #pragma unroll 1
    for (int jb = 0; jb < 32; jb += 4) {
        unsigned long long acc[4][2];
        #pragma unroll
        for (int j = 0; j < 4; j++) { acc[j][0] = bo0; acc[j][1] = bo1; }

        #pragma unroll
        for (int j = 0; j < 4; j++) {
            int row = w * 32 + jb + j;
            const float4* ar = (const float4*)(As + row * H);
            float4 A0 = ar[0], A1 = ar[1], A2 = ar[2], A3 = ar[3];
            float a16[16] = { A0.x,A0.y,A0.z,A0.w, A1.x,A1.y,A1.z,A1.w,
                              A2.x,A2.y,A2.z,A2.w, A3.x,A3.y,A3.z,A3.w };
            #pragma unroll
            for (int p = 0; p < H; p++) {
                unsigned long long ad;
                DUP_F32X2(ad, a16[p]);
                FMA_F32X2(acc[j][0], ad, Tp[p][0], acc[j][0]);
                FMA_F32X2(acc[j][1], ad, Tp[p][1], acc[j][1]);
            }
        }

        float* op = obase + (size_t)jb * rowstride;
        #pragma unroll
        for (int j = 0; j < 4; j++)
            STCS_V2U64(op + (size_t)j * rowstride, acc[j][0], acc[j][1]);
    }
}

// ---------------------------------------------------------------------------
extern "C" void kernel_launch(void* const* d_in, const int* in_sizes, int n_in,
                              void* d_out, int out_size)
{
    const float* feats  = (const float*)d_in[0];
    const float* gamma  = (const float*)d_in[1];
    const float* beta   = (const float*)d_in[2];
    const float* W_in   = (const float*)d_in[3];
    const float* b_in   = (const float*)d_in[4];
    const float* W_out  = (const float*)d_in[5];
    const float* b_out  = (const float*)d_in[6];
    float* out = (float*)d_out;

    float* proj; cudaGetSymbolAddress((void**)&proj, g_proj);
    float* T;    cudaGetSymbolAddress((void**)&T,    g_T);
    float* Wt;   cudaGetSymbolAddress((void**)&Wt,   g_Wt);

    k_wt<<<DOUT, 256>>>(W_out, Wt);
    k_pre<<<(B * N) / 8, 256>>>(feats, gamma, beta, W_in, b_in, Wt, proj, T);
    k_main<<<B * MV * 2, 256>>>(proj, T, b_out, out);
}